// round 10
// baseline (speedup 1.0000x reference)
#include <cuda_runtime.h>
#include <cuda_fp16.h>

// APPNP: h_{k+1} = (1-a) * Dinv(A+I)Dinv * h_k + a * x,  K=5, a=0.8
// g = dinv .* h stored FP16, rows padded to 128B (one L1 line -> 1 wavefront
// per warp-wide row gather). Accumulation fp32. Dim-parallel: lane<24 owns one
// half2/float2 chunk; no reduction. CSR segments padded to multiples of 4 with
// a permanent zero row (index NN). Index int4 loads software-pipelined.

#define NN 100000
#define EE 1600000
#define F2 24               // chunks per row (48 dims / 2)
#define GS 32               // half2 stride per fp16 row (128B padded)
#define CSR_CAP (EE + 3 * NN + 4)
#define ALPHA 0.8f

// ---------------- device scratch (static, no allocation) ----------------
__device__ int     g_ecount[NN];    // zero at every kernel_launch entry (invariant)
__device__ int     g_total;         // zero at entry (invariant)
__device__ float   g_dinv[NN];
__device__ int     g_colstart[NN];
__device__ int     g_colend[NN];    // padded end (multiple-of-4 segment)
__device__ int     g_rank[EE];
__device__ int4    g_csr4[CSR_CAP / 4 + 1];
__device__ __half2 g_bufA[(NN + 1) * GS];   // row NN = permanent zeros
__device__ __half2 g_bufB[(NN + 1) * GS];   // (never written)

// ---------------- preprocessing ----------------
__global__ void k_hist(const int* __restrict__ col) {
    int e = blockIdx.x * blockDim.x + threadIdx.x;
    if (e < EE) g_rank[e] = atomicAdd(&g_ecount[col[e]], 1);
}

__global__ void k_alloc() {
    int v = blockIdx.x * blockDim.x + threadIdx.x;
    if (v < NN) {
        int c  = g_ecount[v];
        int cp = (c + 3) & ~3;
        int p  = atomicAdd(&g_total, cp);       // g_total starts 0 -> p 4-aligned
        g_colstart[v] = p;
        g_colend[v]   = p + cp;
        int* csr = (int*)g_csr4;
        for (int j = c; j < cp; j++) csr[p + j] = NN;   // zero-row padding
        g_dinv[v] = rsqrtf((float)(c + 1));     // +1 self loop
    }
}

// scatter (atomic-free) + g0 = fp16(dinv.*x) + restore zero-invariant
__global__ void k_scatter_fused(const int* __restrict__ row, const int* __restrict__ col,
                                const float2* __restrict__ x2, __half2* __restrict__ g0) {
    int t = blockIdx.x * blockDim.x + threadIdx.x;
    if (t < EE) {
        int p = g_colstart[col[t]] + g_rank[t];
        ((int*)g_csr4)[p] = row[t];
    }
    if (t < NN * F2) {
        int v = t / F2, c = t % F2;
        float s = g_dinv[v];
        float2 a = x2[t];
        g0[v * GS + c] = __floats2half2_rn(a.x * s, a.y * s);
    }
    if (t < NN) g_ecount[t] = 0;       // ecount dead after k_alloc; re-zero
    if (t == 0) g_total = 0;
}

// ---------------- propagation ----------------
// Warp per node; lane<24 owns chunk `lane`. Index int4 prefetched one iter ahead.
template <bool WRITE_H>
__global__ void __launch_bounds__(256, 6) k_propagate(const __half2* __restrict__ gin,
                                                      const float2* __restrict__ x2,
                                                      void* __restrict__ gout_) {
    int v    = (blockIdx.x * blockDim.x + threadIdx.x) >> 5;
    int lane = threadIdx.x & 31;
    if (v >= NN) return;

    int b   = g_colstart[v];
    int end = g_colend[v];                 // multiple-of-4 segment, no tail
    bool act = (lane < F2);

    float2 acc0 = make_float2(0.f, 0.f);
    float2 acc1 = make_float2(0.f, 0.f);

    int4 r = (b < end) ? __ldg(&g_csr4[b >> 2]) : make_int4(NN, NN, NN, NN);
    while (b < end) {
        b += 4;
        int4 rn = (b < end) ? __ldg(&g_csr4[b >> 2]) : make_int4(NN, NN, NN, NN);
        if (act) {
            float2 u0 = __half22float2(__ldg(&gin[r.x * GS + lane]));
            float2 u1 = __half22float2(__ldg(&gin[r.y * GS + lane]));
            float2 u2 = __half22float2(__ldg(&gin[r.z * GS + lane]));
            float2 u3 = __half22float2(__ldg(&gin[r.w * GS + lane]));
            acc0.x += u0.x; acc0.y += u0.y;
            acc1.x += u1.x; acc1.y += u1.y;
            acc0.x += u2.x; acc0.y += u2.y;
            acc1.x += u3.x; acc1.y += u3.y;
        }
        r = rn;
    }

    if (act) {
        float di  = g_dinv[v];
        float2 gv = __half22float2(__ldg(&gin[v * GS + lane]));   // self loop
        float2 xx = __ldg(&x2[v * F2 + lane]);

        float2 h;
        h.x = (1.0f - ALPHA) * (di * (acc0.x + acc1.x + gv.x)) + ALPHA * xx.x;
        h.y = (1.0f - ALPHA) * (di * (acc0.y + acc1.y + gv.y)) + ALPHA * xx.y;

        if (WRITE_H) {
            ((float2*)gout_)[v * F2 + lane] = h;
        } else {   // store g = dinv*h as fp16 for next step
            ((__half2*)gout_)[v * GS + lane] = __floats2half2_rn(h.x * di, h.y * di);
        }
    }
}

// ---------------- launch ----------------
extern "C" void kernel_launch(void* const* d_in, const int* in_sizes, int n_in,
                              void* d_out, int out_size) {
    const float2* x2 = (const float2*)d_in[0];
    const int*    ei = (const int*)d_in[1];
    const int* row = ei;          // edge_index[0]
    const int* col = ei + EE;     // edge_index[1]

    __half2 *pA, *pB;
    cudaGetSymbolAddress((void**)&pA, g_bufA);
    cudaGetSymbolAddress((void**)&pB, g_bufB);

    k_hist<<<(EE + 255) / 256, 256>>>(col);                        // launch 1
    k_alloc<<<(NN + 255) / 256, 256>>>();                          // launch 2
    const int FT = NN * F2;
    k_scatter_fused<<<(FT + 255) / 256, 256>>>(row, col, x2, pA);  // launch 3

    const int PBLK = 256;                       // 8 warps = 8 nodes per block
    const int PGRID = (NN + 7) / 8;             // 12500
    k_propagate<false><<<PGRID, PBLK>>>(pA, x2, pB);    // launch 4 <- profiled
    k_propagate<false><<<PGRID, PBLK>>>(pB, x2, pA);
    k_propagate<false><<<PGRID, PBLK>>>(pA, x2, pB);
    k_propagate<false><<<PGRID, PBLK>>>(pB, x2, pA);
    k_propagate<true ><<<PGRID, PBLK>>>(pA, x2, d_out); // step 5 -> h (fp32)
}

// round 11
// speedup vs baseline: 1.0989x; 1.0989x over previous
#include <cuda_runtime.h>
#include <cuda_fp16.h>

// APPNP: h_{k+1} = (1-a) * Dinv(A+I)Dinv * h_k + a * x,  K=5, a=0.8
// g = dinv .* h stored FP16, rows padded to 128B (1 L1 wavefront per warp-wide
// row gather). Dim-parallel: lane<24 owns one half2 chunk; no reduction.
// Per-quad fp16 adder tree (3 HADD2 + 1 cvt + 2 FADD) to cut issue count ~2x.
// CSR segments padded to multiple of 4 with a permanent zero row (index NN).

#define NN 100000
#define EE 1600000
#define F2 24               // chunks per row (48 dims / 2)
#define GS 32               // half2 stride per fp16 row (128B padded)
#define CSR_CAP (EE + 3 * NN + 4)
#define ALPHA 0.8f

// ---------------- device scratch (static, no allocation) ----------------
__device__ int     g_ecount[NN];    // zero at every kernel_launch entry (invariant)
__device__ int     g_total;         // zero at entry (invariant)
__device__ float   g_dinv[NN];
__device__ int     g_colstart[NN];
__device__ int     g_colend[NN];    // padded end (multiple-of-4 segment)
__device__ int     g_rank[EE];
__device__ int4    g_csr4[CSR_CAP / 4 + 1];
__device__ __half2 g_bufA[(NN + 1) * GS];   // row NN = permanent zeros
__device__ __half2 g_bufB[(NN + 1) * GS];   // (never written)

// ---------------- preprocessing ----------------
__global__ void k_hist(const int* __restrict__ col) {
    int e = blockIdx.x * blockDim.x + threadIdx.x;
    if (e < EE) g_rank[e] = atomicAdd(&g_ecount[col[e]], 1);
}

__global__ void k_alloc() {
    int v = blockIdx.x * blockDim.x + threadIdx.x;
    if (v < NN) {
        int c  = g_ecount[v];
        int cp = (c + 3) & ~3;
        int p  = atomicAdd(&g_total, cp);       // g_total starts 0 -> p 4-aligned
        g_colstart[v] = p;
        g_colend[v]   = p + cp;
        int* csr = (int*)g_csr4;
        for (int j = c; j < cp; j++) csr[p + j] = NN;   // zero-row padding
        g_dinv[v] = rsqrtf((float)(c + 1));     // +1 self loop
    }
}

// scatter (atomic-free) + g0 = fp16(dinv.*x) + restore zero-invariant
__global__ void k_scatter_fused(const int* __restrict__ row, const int* __restrict__ col,
                                const float2* __restrict__ x2, __half2* __restrict__ g0) {
    int t = blockIdx.x * blockDim.x + threadIdx.x;
    if (t < EE) {
        int p = g_colstart[col[t]] + g_rank[t];
        ((int*)g_csr4)[p] = row[t];
    }
    if (t < NN * F2) {
        int v = t / F2, c = t % F2;
        float s = g_dinv[v];
        float2 a = x2[t];
        g0[v * GS + c] = __floats2half2_rn(a.x * s, a.y * s);
    }
    if (t < NN) g_ecount[t] = 0;       // ecount dead after k_alloc; re-zero
    if (t == 0) g_total = 0;
}

// ---------------- propagation ----------------
// Warp per node; lane<24 owns chunk `lane`. Index int4 prefetched one iter ahead.
// Edge quad summed with fp16 tree, then one fp32 accumulate.
template <bool WRITE_H>
__global__ void __launch_bounds__(256, 6) k_propagate(const __half2* __restrict__ gin,
                                                      const float2* __restrict__ x2,
                                                      void* __restrict__ gout_) {
    int v    = (blockIdx.x * blockDim.x + threadIdx.x) >> 5;
    int lane = threadIdx.x & 31;
    if (v >= NN) return;

    int b   = g_colstart[v];
    int end = g_colend[v];                 // multiple-of-4 segment, no tail
    bool act = (lane < F2);

    float2 acc = make_float2(0.f, 0.f);

    int4 r = (b < end) ? __ldg(&g_csr4[b >> 2]) : make_int4(NN, NN, NN, NN);
    while (b < end) {
        b += 4;
        int4 rn = (b < end) ? __ldg(&g_csr4[b >> 2]) : make_int4(NN, NN, NN, NN);
        if (act) {
            __half2 u0 = __ldg(&gin[r.x * GS + lane]);
            __half2 u1 = __ldg(&gin[r.y * GS + lane]);
            __half2 u2 = __ldg(&gin[r.z * GS + lane]);
            __half2 u3 = __ldg(&gin[r.w * GS + lane]);
            __half2 s  = __hadd2(__hadd2(u0, u1), __hadd2(u2, u3));
            float2  f  = __half22float2(s);
            acc.x += f.x;
            acc.y += f.y;
        }
        r = rn;
    }

    if (act) {
        float di  = g_dinv[v];
        float2 gv = __half22float2(__ldg(&gin[v * GS + lane]));   // self loop
        float2 xx = __ldg(&x2[v * F2 + lane]);

        float2 h;
        h.x = (1.0f - ALPHA) * (di * (acc.x + gv.x)) + ALPHA * xx.x;
        h.y = (1.0f - ALPHA) * (di * (acc.y + gv.y)) + ALPHA * xx.y;

        if (WRITE_H) {
            ((float2*)gout_)[v * F2 + lane] = h;
        } else {   // store g = dinv*h as fp16 for next step
            ((__half2*)gout_)[v * GS + lane] = __floats2half2_rn(h.x * di, h.y * di);
        }
    }
}

// ---------------- launch ----------------
extern "C" void kernel_launch(void* const* d_in, const int* in_sizes, int n_in,
                              void* d_out, int out_size) {
    const float2* x2 = (const float2*)d_in[0];
    const int*    ei = (const int*)d_in[1];
    const int* row = ei;          // edge_index[0]
    const int* col = ei + EE;     // edge_index[1]

    __half2 *pA, *pB;
    cudaGetSymbolAddress((void**)&pA, g_bufA);
    cudaGetSymbolAddress((void**)&pB, g_bufB);

    k_hist<<<(EE + 255) / 256, 256>>>(col);                        // launch 1
    k_alloc<<<(NN + 255) / 256, 256>>>();                          // launch 2
    const int FT = NN * F2;
    k_scatter_fused<<<(FT + 255) / 256, 256>>>(row, col, x2, pA);  // launch 3

    const int PBLK = 256;                       // 8 warps = 8 nodes per block
    const int PGRID = (NN + 7) / 8;             // 12500
    k_propagate<false><<<PGRID, PBLK>>>(pA, x2, pB);    // launch 4 <- profiled
    k_propagate<false><<<PGRID, PBLK>>>(pB, x2, pA);
    k_propagate<false><<<PGRID, PBLK>>>(pA, x2, pB);
    k_propagate<false><<<PGRID, PBLK>>>(pB, x2, pA);
    k_propagate<true ><<<PGRID, PBLK>>>(pA, x2, d_out); // step 5 -> h (fp32)
}

// round 12
// speedup vs baseline: 1.2610x; 1.1475x over previous
#include <cuda_runtime.h>
#include <cuda_fp16.h>

// APPNP: h_{k+1} = (1-a) * Dinv(A+I)Dinv * h_k + a * x,  K=5, a=0.8
// g = dinv .* h stored FP16, rows padded to 128B (1 L1 wavefront per warp-wide
// row gather). Dim-parallel: lane<24 owns one half2 chunk; no reduction.
// Per-quad fp16 adder tree (3 HADD2 + cvt + 2 FADD). Lean registers:
// no index pipeline, __launch_bounds__(256,8) -> 32-reg cap for ~80% occ.

#define NN 100000
#define EE 1600000
#define F2 24               // chunks per row (48 dims / 2)
#define GS 32               // half2 stride per fp16 row (128B padded)
#define CSR_CAP (EE + 3 * NN + 4)
#define ALPHA 0.8f

// ---------------- device scratch (static, no allocation) ----------------
__device__ int     g_ecount[NN];    // zero at every kernel_launch entry (invariant)
__device__ int     g_total;         // zero at entry (invariant)
__device__ float   g_dinv[NN];
__device__ int     g_colstart[NN];
__device__ int     g_colend[NN];    // padded end (multiple-of-4 segment)
__device__ int     g_rank[EE];
__device__ int4    g_csr4[CSR_CAP / 4 + 1];
__device__ __half2 g_bufA[(NN + 1) * GS];   // row NN = permanent zeros
__device__ __half2 g_bufB[(NN + 1) * GS];   // (never written)

// ---------------- preprocessing ----------------
__global__ void k_hist(const int* __restrict__ col) {
    int e = blockIdx.x * blockDim.x + threadIdx.x;
    if (e < EE) g_rank[e] = atomicAdd(&g_ecount[col[e]], 1);
}

__global__ void k_alloc() {
    int v = blockIdx.x * blockDim.x + threadIdx.x;
    if (v < NN) {
        int c  = g_ecount[v];
        int cp = (c + 3) & ~3;
        int p  = atomicAdd(&g_total, cp);       // g_total starts 0 -> p 4-aligned
        g_colstart[v] = p;
        g_colend[v]   = p + cp;
        int* csr = (int*)g_csr4;
        for (int j = c; j < cp; j++) csr[p + j] = NN;   // zero-row padding
        g_dinv[v] = rsqrtf((float)(c + 1));     // +1 self loop
    }
}

// scatter (atomic-free) + g0 = fp16(dinv.*x) + restore zero-invariant
__global__ void k_scatter_fused(const int* __restrict__ row, const int* __restrict__ col,
                                const float2* __restrict__ x2, __half2* __restrict__ g0) {
    int t = blockIdx.x * blockDim.x + threadIdx.x;
    if (t < EE) {
        int p = g_colstart[col[t]] + g_rank[t];
        ((int*)g_csr4)[p] = row[t];
    }
    if (t < NN * F2) {
        int v = t / F2, c = t % F2;
        float s = g_dinv[v];
        float2 a = x2[t];
        g0[v * GS + c] = __floats2half2_rn(a.x * s, a.y * s);
    }
    if (t < NN) g_ecount[t] = 0;       // ecount dead after k_alloc; re-zero
    if (t == 0) g_total = 0;
}

// ---------------- propagation ----------------
// Warp per node; lane<24 owns chunk `lane`.
// Edge quad summed with fp16 tree, then one fp32 accumulate.
template <bool WRITE_H>
__global__ void __launch_bounds__(256, 8) k_propagate(const __half2* __restrict__ gin,
                                                      const float2* __restrict__ x2,
                                                      void* __restrict__ gout_) {
    int v    = (blockIdx.x * blockDim.x + threadIdx.x) >> 5;
    int lane = threadIdx.x & 31;
    if (v >= NN) return;

    int b   = g_colstart[v];
    int end = g_colend[v];                 // multiple-of-4 segment, no tail
    bool act = (lane < F2);

    float2 acc = make_float2(0.f, 0.f);

    for (; b < end; b += 4) {
        int4 r = __ldg(&g_csr4[b >> 2]);   // uniform: 4 edge indices, 1 wavefront
        if (act) {
            __half2 u0 = __ldg(&gin[r.x * GS + lane]);
            __half2 u1 = __ldg(&gin[r.y * GS + lane]);
            __half2 u2 = __ldg(&gin[r.z * GS + lane]);
            __half2 u3 = __ldg(&gin[r.w * GS + lane]);
            __half2 s  = __hadd2(__hadd2(u0, u1), __hadd2(u2, u3));
            float2  f  = __half22float2(s);
            acc.x += f.x;
            acc.y += f.y;
        }
    }

    if (act) {
        float di  = g_dinv[v];
        float2 gv = __half22float2(__ldg(&gin[v * GS + lane]));   // self loop
        float2 xx = __ldg(&x2[v * F2 + lane]);

        float2 h;
        h.x = (1.0f - ALPHA) * (di * (acc.x + gv.x)) + ALPHA * xx.x;
        h.y = (1.0f - ALPHA) * (di * (acc.y + gv.y)) + ALPHA * xx.y;

        if (WRITE_H) {
            ((float2*)gout_)[v * F2 + lane] = h;
        } else {   // store g = dinv*h as fp16 for next step
            ((__half2*)gout_)[v * GS + lane] = __floats2half2_rn(h.x * di, h.y * di);
        }
    }
}

// ---------------- launch ----------------
extern "C" void kernel_launch(void* const* d_in, const int* in_sizes, int n_in,
                              void* d_out, int out_size) {
    const float2* x2 = (const float2*)d_in[0];
    const int*    ei = (const int*)d_in[1];
    const int* row = ei;          // edge_index[0]
    const int* col = ei + EE;     // edge_index[1]

    __half2 *pA, *pB;
    cudaGetSymbolAddress((void**)&pA, g_bufA);
    cudaGetSymbolAddress((void**)&pB, g_bufB);

    k_hist<<<(EE + 255) / 256, 256>>>(col);                        // launch 1
    k_alloc<<<(NN + 255) / 256, 256>>>();                          // launch 2
    const int FT = NN * F2;
    k_scatter_fused<<<(FT + 255) / 256, 256>>>(row, col, x2, pA);  // launch 3

    const int PBLK = 256;                       // 8 warps = 8 nodes per block
    const int PGRID = (NN + 7) / 8;             // 12500
    k_propagate<false><<<PGRID, PBLK>>>(pA, x2, pB);    // launch 4 <- profiled
    k_propagate<false><<<PGRID, PBLK>>>(pB, x2, pA);
    k_propagate<false><<<PGRID, PBLK>>>(pA, x2, pB);
    k_propagate<false><<<PGRID, PBLK>>>(pB, x2, pA);
    k_propagate<true ><<<PGRID, PBLK>>>(pA, x2, d_out); // step 5 -> h (fp32)
}